// round 2
// baseline (speedup 1.0000x reference)
#include <cuda_runtime.h>

typedef unsigned long long ULL;

__device__ __forceinline__ ULL pack2(float a, float b){
    ULL r; asm("mov.b64 %0, {%1, %2};" : "=l"(r) : "f"(a), "f"(b)); return r;
}
__device__ __forceinline__ void unpack2(ULL v, float& a, float& b){
    asm("mov.b64 {%0, %1}, %2;" : "=f"(a), "=f"(b) : "l"(v));
}
// Packed dual-fp32 FMA (Blackwell FFMA2) — ptxas will not auto-fuse this, must be PTX.
__device__ __forceinline__ ULL ffma2(ULL a, ULL b, ULL c){
    ULL d; asm("fma.rn.f32x2 %0, %1, %2, %3;" : "=l"(d) : "l"(a), "l"(b), "l"(c)); return d;
}

__device__ __forceinline__ float celu1(float v){
    return v > 0.f ? v : (__expf(v) - 1.f);
}

// Per-point segment starts (out_index is sorted). g_start[n] = lower_bound(out_index, n).
__device__ int g_start[32769];

__global__ void starts_kernel(const int* __restrict__ out_index, int E, int Npts){
    int i = blockIdx.x * blockDim.x + threadIdx.x;
    if (i > Npts) return;
    int lo = 0, hi = E;
    while (lo < hi){ int mid = (lo + hi) >> 1; if (out_index[mid] < i) lo = mid + 1; else hi = mid; }
    g_start[i] = lo;
}

__global__ __launch_bounds__(256, 2)
void pointconv_kernel(const float* __restrict__ x_in, const float* __restrict__ pos_in,
                      const float* __restrict__ pos_out, const int* __restrict__ in_index,
                      const float* __restrict__ W1, const float* __restrict__ W2,
                      const float* __restrict__ W3, const float* __restrict__ b3,
                      float* __restrict__ out, int Npts)
{
    __shared__ float P_s[8][1024];   // staged 16x64 accumulators, one per warp/point

    const int w = threadIdx.x >> 5;
    const int l = threadIdx.x & 31;
    const int n = blockIdx.x * 8 + w;

    ULL acc[16];
    #pragma unroll
    for (int c = 0; c < 16; ++c) acc[c] = 0ull;

    if (n < Npts) {
        const int s     = g_start[n];
        const int cnt   = g_start[n + 1] - s;
        const float inv = cnt > 0 ? 1.f / (float)cnt : 0.f;
        const int lim   = cnt < 64 ? cnt : 64;   // reference drops edges past K=64 slots

        // W1 column for this lane's h1 element (lanes 0-15 meaningful, 16-31 harmless dup)
        const int j16 = l & 15;
        const float w1c0 = W1[j16], w1c1 = W1[16 + j16], w1c2 = W1[32 + j16];

        // W2 columns (l, l+32) held packed in registers, loaded once
        ULL w2col[16];
        #pragma unroll
        for (int j = 0; j < 16; ++j)
            w2col[j] = pack2(W2[j * 64 + l], W2[j * 64 + l + 32]);

        const float pox = pos_out[n * 3], poy = pos_out[n * 3 + 1], poz = pos_out[n * 3 + 2];

        for (int t = 0; t < lim; ++t) {
            const int idx = in_index[s + t];
            const float d0 = pos_in[idx * 3]     - pox;
            const float d1 = pos_in[idx * 3 + 1] - poy;
            const float d2 = pos_in[idx * 3 + 2] - poz;

            // h1[j16] = celu(d . W1[:, j16]) — computed once per edge across lanes 0-15
            const float h = celu1(fmaf(d2, w1c2, fmaf(d1, w1c1, d0 * w1c0)));
            // normalized gathered feature, one channel per lane (0-15)
            const float x = x_in[idx * 16 + j16] * inv;

            // M[l], M[l+32] = celu(h1 . W2[:, {l,l+32}])   (16 shfl + 16 FFMA2)
            ULL m2 = 0ull;
            #pragma unroll
            for (int j = 0; j < 16; ++j) {
                const float hj = __shfl_sync(0xffffffffu, h, j);
                m2 = ffma2(pack2(hj, hj), w2col[j], m2);
            }
            float ma, mb; unpack2(m2, ma, mb);
            m2 = pack2(celu1(ma), celu1(mb));

            // acc[c][{l,l+32}] += x[c] * M[{l,l+32}]        (16 shfl + 16 FFMA2)
            #pragma unroll
            for (int c = 0; c < 16; ++c) {
                const float xc = __shfl_sync(0xffffffffu, x, c);
                acc[c] = ffma2(pack2(xc, xc), m2, acc[c]);
            }
        }
    }

    // Stage P[c*64 + m] into smem (product.reshape(C_IN*C_MID) layout)
    #pragma unroll
    for (int c = 0; c < 16; ++c) {
        float a, b; unpack2(acc[c], a, b);
        P_s[w][c * 64 + l]      = a;
        P_s[w][c * 64 + l + 32] = b;
    }
    __syncthreads();

    // Fused epilogue GEMM: out[n] = P @ W3 + b3. Thread -> point w, outputs (2l, 2l+1).
    if (n < Npts) {
        ULL ob = 0ull;
        const float* Pp = P_s[w];
        const float* W3l = W3 + 2 * l;
        #pragma unroll 4
        for (int i = 0; i < 1024; i += 4) {
            const float4 pv = *(const float4*)(Pp + i);   // LDS.128 broadcast
            ob = ffma2(pack2(pv.x, pv.x), *(const ULL*)(W3l + (i    ) * 64), ob);
            ob = ffma2(pack2(pv.y, pv.y), *(const ULL*)(W3l + (i + 1) * 64), ob);
            ob = ffma2(pack2(pv.z, pv.z), *(const ULL*)(W3l + (i + 2) * 64), ob);
            ob = ffma2(pack2(pv.w, pv.w), *(const ULL*)(W3l + (i + 3) * 64), ob);
        }
        float oa, obb; unpack2(ob, oa, obb);
        out[n * 64 + 2 * l]     = oa  + b3[2 * l];
        out[n * 64 + 2 * l + 1] = obb + b3[2 * l + 1];
    }
}

extern "C" void kernel_launch(void* const* d_in, const int* in_sizes, int n_in,
                              void* d_out, int out_size)
{
    const float* x_in    = (const float*)d_in[0];
    const float* pos_in  = (const float*)d_in[1];
    const float* pos_out = (const float*)d_in[2];
    const int*  in_index = (const int*)  d_in[3];
    const int* out_index = (const int*)  d_in[4];
    const float* W1 = (const float*)d_in[5];
    const float* W2 = (const float*)d_in[6];
    const float* W3 = (const float*)d_in[7];
    const float* b3 = (const float*)d_in[8];
    float* out = (float*)d_out;

    const int E    = in_sizes[3];
    const int Npts = in_sizes[0] / 16;   // x_in is [N, 16]

    starts_kernel<<<(Npts + 256) / 256, 256>>>(out_index, E, Npts);
    pointconv_kernel<<<(Npts + 7) / 8, 256>>>(x_in, pos_in, pos_out, in_index,
                                              W1, W2, W3, b3, out, Npts);
}

// round 3
// speedup vs baseline: 1.3598x; 1.3598x over previous
#include <cuda_runtime.h>

typedef unsigned long long ULL;

__device__ __forceinline__ ULL pack2(float a, float b){
    ULL r; asm("mov.b64 %0, {%1, %2};" : "=l"(r) : "f"(a), "f"(b)); return r;
}
__device__ __forceinline__ void unpack2(ULL v, float& a, float& b){
    asm("mov.b64 {%0, %1}, %2;" : "=f"(a), "=f"(b) : "l"(v));
}
// Packed dual-fp32 FMA / ADD (Blackwell f32x2) — ptxas never auto-fuses; must be PTX.
__device__ __forceinline__ ULL ffma2(ULL a, ULL b, ULL c){
    ULL d; asm("fma.rn.f32x2 %0, %1, %2, %3;" : "=l"(d) : "l"(a), "l"(b), "l"(c)); return d;
}
__device__ __forceinline__ ULL fadd2(ULL a, ULL b){
    ULL d; asm("add.rn.f32x2 %0, %1, %2;" : "=l"(d) : "l"(a), "l"(b)); return d;
}

__device__ __forceinline__ float celu1(float v){
    return v > 0.f ? v : (__expf(v) - 1.f);
}

// Per-point segment starts (out_index is sorted). g_start[n] = lower_bound(out_index, n).
__device__ int g_start[32769];

__global__ void starts_kernel(const int* __restrict__ out_index, int E, int Npts){
    int i = blockIdx.x * blockDim.x + threadIdx.x;
    if (i > Npts) return;
    int lo = 0, hi = E;
    while (lo < hi){ int mid = (lo + hi) >> 1; if (out_index[mid] < i) lo = mid + 1; else hi = mid; }
    g_start[i] = lo;
}

__global__ __launch_bounds__(256, 2)
void pointconv_kernel(const float* __restrict__ x_in, const float* __restrict__ pos_in,
                      const float* __restrict__ pos_out, const int* __restrict__ in_index,
                      const float* __restrict__ W1, const float* __restrict__ W2,
                      const float* __restrict__ W3, const float* __restrict__ b3,
                      float* __restrict__ out, int Npts)
{
    // Pd[p][k] holds P value DUPLICATED as (v,v) in a 64-bit word -> the scalar
    // operand of the epilogue ffma2 loads pre-packed (no per-FMA dup MOV).
    extern __shared__ ULL Pd[];            // [8][1024] = 64 KB

    const int w = threadIdx.x >> 5;
    const int l = threadIdx.x & 31;
    const int n = blockIdx.x * 8 + w;

    ULL acc[16];
    #pragma unroll
    for (int c = 0; c < 16; ++c) acc[c] = 0ull;

    if (n < Npts) {
        const int s     = g_start[n];
        const int cnt   = g_start[n + 1] - s;
        const float inv = cnt > 0 ? 1.f / (float)cnt : 0.f;
        const int lim   = cnt < 64 ? cnt : 64;   // reference drops edges past K=64 slots

        const int j16 = l & 15;
        const float w1c0 = W1[j16], w1c1 = W1[16 + j16], w1c2 = W1[32 + j16];

        ULL w2col[16];
        #pragma unroll
        for (int j = 0; j < 16; ++j)
            w2col[j] = pack2(W2[j * 64 + l], W2[j * 64 + l + 32]);

        const float pox = pos_out[n * 3], poy = pos_out[n * 3 + 1], poz = pos_out[n * 3 + 2];

        for (int t = 0; t < lim; ++t) {
            const int idx = in_index[s + t];
            const float d0 = pos_in[idx * 3]     - pox;
            const float d1 = pos_in[idx * 3 + 1] - poy;
            const float d2 = pos_in[idx * 3 + 2] - poz;

            const float h = celu1(fmaf(d2, w1c2, fmaf(d1, w1c1, d0 * w1c0)));
            const float x = x_in[idx * 16 + j16] * inv;

            ULL m2 = 0ull;
            #pragma unroll
            for (int j = 0; j < 16; ++j) {
                const float hj = __shfl_sync(0xffffffffu, h, j);
                m2 = ffma2(pack2(hj, hj), w2col[j], m2);
            }
            float ma, mb; unpack2(m2, ma, mb);
            m2 = pack2(celu1(ma), celu1(mb));

            #pragma unroll
            for (int c = 0; c < 16; ++c) {
                const float xc = __shfl_sync(0xffffffffu, x, c);
                acc[c] = ffma2(pack2(xc, xc), m2, acc[c]);
            }
        }
    }

    // Stage P (duplicated) into smem: Pd[w][c*64 + m] = (P, P)
    ULL* Pw = Pd + w * 1024;
    #pragma unroll
    for (int c = 0; c < 16; ++c) {
        float a, b; unpack2(acc[c], a, b);
        Pw[c * 64 + l]      = pack2(a, a);
        Pw[c * 64 + l + 32] = pack2(b, b);
    }
    __syncthreads();

    // Cooperative epilogue GEMM: out[8 pts][64] = P[8][1024] @ W3[1024][64] + b3.
    // Warp w covers k in [128w, 128w+128) for ALL 8 points; lane owns col pair (2l, 2l+1).
    // W3 is read exactly once per block (8x reuse vs per-point streaming).
    ULL acc2[8];
    #pragma unroll
    for (int p = 0; p < 8; ++p) acc2[p] = 0ull;

    const int k0 = w * 128;
    const float* W3l = W3 + 2 * l;
    #pragma unroll 1
    for (int kk = 0; kk < 128; kk += 2) {
        const int k = k0 + kk;
        ULL pv0[8], pv1[8];
        #pragma unroll
        for (int p = 0; p < 8; ++p) {
            // broadcast LDS.128: two dup'd P values (k, k+1) for point p
            ulonglong2 v = *(const ulonglong2*)(Pd + p * 1024 + k);
            pv0[p] = v.x; pv1[p] = v.y;
        }
        const ULL w3a = *(const ULL*)(W3l + (k    ) * 64);
        const ULL w3b = *(const ULL*)(W3l + (k + 1) * 64);
        #pragma unroll
        for (int p = 0; p < 8; ++p) acc2[p] = ffma2(pv0[p], w3a, acc2[p]);
        #pragma unroll
        for (int p = 0; p < 8; ++p) acc2[p] = ffma2(pv1[p], w3b, acc2[p]);
    }

    // Reduce partials across the 8 warps (k-ranges) through smem overlay.
    __syncthreads();                       // all Pd reads done
    ULL* red = Pd;                         // red[w][p][l], 8*8*32 ULL = 16 KB
    #pragma unroll
    for (int p = 0; p < 8; ++p) red[(w * 8 + p) * 32 + l] = acc2[p];
    __syncthreads();

    // Thread (w,l): final sum for point p=w, cols (2l, 2l+1).
    if (n < Npts) {
        ULL s2 = 0ull;
        #pragma unroll
        for (int ww = 0; ww < 8; ++ww) s2 = fadd2(s2, red[(ww * 8 + w) * 32 + l]);
        float oa, ob; unpack2(s2, oa, ob);
        out[n * 64 + 2 * l]     = oa + b3[2 * l];
        out[n * 64 + 2 * l + 1] = ob + b3[2 * l + 1];
    }
}

extern "C" void kernel_launch(void* const* d_in, const int* in_sizes, int n_in,
                              void* d_out, int out_size)
{
    const float* x_in    = (const float*)d_in[0];
    const float* pos_in  = (const float*)d_in[1];
    const float* pos_out = (const float*)d_in[2];
    const int*  in_index = (const int*)  d_in[3];
    const int* out_index = (const int*)  d_in[4];
    const float* W1 = (const float*)d_in[5];
    const float* W2 = (const float*)d_in[6];
    const float* W3 = (const float*)d_in[7];
    const float* b3 = (const float*)d_in[8];
    float* out = (float*)d_out;

    const int E    = in_sizes[3];
    const int Npts = in_sizes[0] / 16;   // x_in is [N, 16]

    cudaFuncSetAttribute(pointconv_kernel,
                         cudaFuncAttributeMaxDynamicSharedMemorySize, 65536);

    starts_kernel<<<(Npts + 256) / 256, 256>>>(out_index, E, Npts);
    pointconv_kernel<<<(Npts + 7) / 8, 256, 65536>>>(x_in, pos_in, pos_out, in_index,
                                                     W1, W2, W3, b3, out, Npts);
}